// round 12
// baseline (speedup 1.0000x reference)
#include <cuda_runtime.h>
#include <math.h>

#define N_BOX     1048576
#define NUM_PTS   9
#define L_CONST   3.0f
#define EPS_F     1e-6f
#define GMM_EPS_F 1e-6f

#define BOX_PER_WCHUNK 16
#define WPRED_F4   (BOX_PER_WCHUNK * 18 / 4)   // 72
#define WTARG_F4   (BOX_PER_WCHUNK * 8 / 4)    // 32
#define WSTAGE_F4  (WPRED_F4 + WTARG_F4)       // 104
#define NSTAGE     2
#define NWCHUNK    (N_BOX / BOX_PER_WCHUNK)    // 65536
#define GRID_BLKS  592                         // 4 * 148 blocks... now 8 CTA/SM resident
#define WARPS_PER_BLK 8
#define TOTAL_WARPS  (GRID_BLKS * WARPS_PER_BLK)   // 4736

__global__ void zero_out_kernel(float* out) { out[0] = 0.0f; }

__device__ __forceinline__ void cp_async16(void* smem_ptr, const void* gptr) {
    unsigned saddr = (unsigned)__cvta_generic_to_shared(smem_ptr);
    asm volatile("cp.async.cg.shared.global [%0], [%1], 16;\n"
                 :: "r"(saddr), "l"(gptr));
}
__device__ __forceinline__ void cp_commit() {
    asm volatile("cp.async.commit_group;\n" ::: "memory");
}
template <int N>
__device__ __forceinline__ void cp_wait() {
    asm volatile("cp.async.wait_group %0;\n" :: "n"(N) : "memory");
}

// Warp-cooperative staging of one 16-box chunk: 72 pred float4 + 32 targ float4.
__device__ __forceinline__ void issue_wchunk(float4* st, const float4* gp,
                                             const float4* gt, int lane) {
    #pragma unroll
    for (int j = 0; j < 2; j++)
        cp_async16(&st[lane + 32 * j], &gp[lane + 32 * j]);
    if (lane < WPRED_F4 - 2 * 32)                       // remaining 8
        cp_async16(&st[lane + 64], &gp[lane + 64]);
    cp_async16(&st[WPRED_F4 + lane], &gt[lane]);
    cp_commit();
}

__device__ __forceinline__ float box_loss(const float* s_pred, const float* s_targ,
                                          int lane) {
    const float2* p2 = reinterpret_cast<const float2*>(s_pred + lane * 18);
    float px[NUM_PTS], py[NUM_PTS];
    #pragma unroll
    for (int k = 0; k < NUM_PTS; k++) {
        float2 v = p2[k];
        px[k] = v.x; py[k] = v.y;
    }
    const float4* t4 = reinterpret_cast<const float4*>(s_targ + lane * 8);
    float4 ta = t4[0];
    float4 tb = t4[1];

    float sx = 0.f, sy = 0.f;
    #pragma unroll
    for (int k = 0; k < NUM_PTS; k++) { sx += px[k]; sy += py[k]; }
    const float inv_np = 1.0f / (float)NUM_PTS;
    float mux = sx * inv_np, muy = sy * inv_np;

    float cxx = 0.f, cxy = 0.f, cyy = 0.f;
    #pragma unroll
    for (int k = 0; k < NUM_PTS; k++) {
        float dx = px[k] - mux, dy = py[k] - muy;
        cxx += dx * dx; cxy += dx * dy; cyy += dy * dy;
    }
    cxx = cxx * inv_np + GMM_EPS_F;
    cxy = cxy * inv_np;
    cyy = cyy * inv_np + GMM_EPS_F;

    float tmux = (ta.x + ta.z + tb.x + tb.z) * 0.25f;
    float tmuy = (ta.y + ta.w + tb.y + tb.w) * 0.25f;

    float e1x = ta.z - ta.x, e1y = ta.w - ta.y;
    float e2x = tb.x - ta.z, e2y = tb.y - ta.w;
    float w = e1x * e1x + e1y * e1y;
    float h = e2x * e2x + e2y * e2y;
    float inv_sw = rsqrtf(w);
    float c = e1x * inv_sw, s = e1y * inv_sw;

    const float dscale = 1.0f / (4.0f * L_CONST * L_CONST);
    float d0 = w * dscale, d1 = h * dscale;

    float c2 = c * c, s2 = s * s, cs = c * s;
    float t00 = c2 * d0 + s2 * d1;
    float t01 = cs * (d0 - d1);
    float t11 = s2 * d0 + c2 * d1;

    float t_det = t00 * t11 - t01 * t01;
    float p_det = cxx * cyy - cxy * cxy;

    float inv_tdet = 1.0f / t_det;
    float i00 =  t11 * inv_tdet;
    float i01 = -t01 * inv_tdet;
    float i11 =  t00 * inv_tdet;

    float dx = mux - tmux, dy = muy - tmuy;
    float term1 = dx * (i00 * dx + i01 * dy) + dy * (i01 * dx + i11 * dy);
    float trace = i00 * cxx + 2.0f * i01 * cxy + i11 * cyy;

    float term2 = trace + logf(t_det / p_det);
    float kld = 0.5f * (term1 + term2) - 1.0f;
    float kl_agg = fmaxf(kld, EPS_F);
    return 1.0f - 1.0f / (2.0f + sqrtf(kl_agg));
}

__global__ void __launch_bounds__(256, 8) kld_loss_kernel(
    const float* __restrict__ pred,
    const float* __restrict__ target,
    float* __restrict__ out)
{
    // per-warp double-buffered slabs: 8 warps * 2 stages * 104 float4 = 26624 B
    extern __shared__ float4 s4[];

    const int tid  = threadIdx.x;
    const int lane = tid & 31;
    const int wid  = tid >> 5;
    float4* wslab = s4 + wid * (NSTAGE * WSTAGE_F4);

    const float4* gp_base = reinterpret_cast<const float4*>(pred);
    const float4* gt_base = reinterpret_cast<const float4*>(target);

    // warp-autonomous grid stride over 16-box chunks
    int c    = blockIdx.x * WARPS_PER_BLK + wid;
    int next = c + TOTAL_WARPS;
    int buf  = 0;

    issue_wchunk(wslab, gp_base + (size_t)c * WPRED_F4,
                        gt_base + (size_t)c * WTARG_F4, lane);

    float acc = 0.0f;

    while (c < NWCHUNK) {
        if (next < NWCHUNK) {
            issue_wchunk(wslab + (buf ^ 1) * WSTAGE_F4,
                         gp_base + (size_t)next * WPRED_F4,
                         gt_base + (size_t)next * WTARG_F4, lane);
            cp_wait<1>();
        } else {
            cp_wait<0>();
        }
        __syncwarp();

        if (lane < BOX_PER_WCHUNK) {
            const float* stage = reinterpret_cast<const float*>(wslab + buf * WSTAGE_F4);
            acc += box_loss(stage, stage + WPRED_F4 * 4, lane);
        }
        __syncwarp();   // all lanes done reading before this stage is reused

        c = next;
        next += TOTAL_WARPS;
        buf ^= 1;
    }

    // ---- block reduction ----
    #pragma unroll
    for (int off = 16; off > 0; off >>= 1)
        acc += __shfl_down_sync(0xFFFFFFFFu, acc, off);

    __shared__ float warp_sums[WARPS_PER_BLK];
    if (lane == 0) warp_sums[wid] = acc;
    __syncthreads();

    if (wid == 0) {
        float v = (lane < WARPS_PER_BLK) ? warp_sums[lane] : 0.0f;
        #pragma unroll
        for (int off = 4; off > 0; off >>= 1)
            v += __shfl_down_sync(0xFFFFFFFFu, v, off);
        if (lane == 0)
            atomicAdd(out, v * (1.0f / (float)N_BOX));
    }
}

extern "C" void kernel_launch(void* const* d_in, const int* in_sizes, int n_in,
                              void* d_out, int out_size) {
    const float* pred   = (const float*)d_in[0];
    const float* target = (const float*)d_in[1];
    float* out = (float*)d_out;

    zero_out_kernel<<<1, 1>>>(out);
    kld_loss_kernel<<<GRID_BLKS, 256,
                      WARPS_PER_BLK * NSTAGE * WSTAGE_F4 * sizeof(float4)>>>(
        pred, target, out);
}

// round 15
// speedup vs baseline: 1.4776x; 1.4776x over previous
#include <cuda_runtime.h>
#include <math.h>

#define N_BOX     1048576
#define NUM_PTS   9
#define L_CONST   3.0f
#define EPS_F     1e-6f
#define GMM_EPS_F 1e-6f

#define BOX_PER_WCHUNK 32
#define WPRED_F4   (BOX_PER_WCHUNK * 18 / 4)   // 144
#define WTARG_F4   (BOX_PER_WCHUNK * 8 / 4)    // 64
#define WSTAGE_F4  (WPRED_F4 + WTARG_F4)       // 208
#define NSTAGE     2
#define NWCHUNK    (N_BOX / BOX_PER_WCHUNK)    // 32768
#define GRID_BLKS  592                         // persistent single wave
#define WARPS_PER_BLK 8
#define TOTAL_WARPS  (GRID_BLKS * WARPS_PER_BLK)   // 4736

__global__ void zero_out_kernel(float* out) { out[0] = 0.0f; }

__device__ __forceinline__ void cp_async16(void* smem_ptr, const void* gptr) {
    unsigned saddr = (unsigned)__cvta_generic_to_shared(smem_ptr);
    asm volatile("cp.async.cg.shared.global [%0], [%1], 16;\n"
                 :: "r"(saddr), "l"(gptr));
}
__device__ __forceinline__ void cp_commit() {
    asm volatile("cp.async.commit_group;\n" ::: "memory");
}
template <int N>
__device__ __forceinline__ void cp_wait() {
    asm volatile("cp.async.wait_group %0;\n" :: "n"(N) : "memory");
}

// Warp-cooperative staging of one 32-box chunk (pred + target).
__device__ __forceinline__ void issue_wchunk(float4* st, const float4* gp,
                                             const float4* gt, int lane) {
    #pragma unroll
    for (int j = 0; j < 4; j++)
        cp_async16(&st[lane + 32 * j], &gp[lane + 32 * j]);
    if (lane < WPRED_F4 - 4 * 32)                       // remaining 16
        cp_async16(&st[lane + 128], &gp[lane + 128]);
    #pragma unroll
    for (int j = 0; j < 2; j++)
        cp_async16(&st[WPRED_F4 + lane + 32 * j], &gt[lane + 32 * j]);
    cp_commit();
}

__device__ __forceinline__ float box_loss(const float* s_pred, const float* s_targ,
                                          int lane) {
    const float2* p2 = reinterpret_cast<const float2*>(s_pred + lane * 18);
    float px[NUM_PTS], py[NUM_PTS];
    #pragma unroll
    for (int k = 0; k < NUM_PTS; k++) {
        float2 v = p2[k];
        px[k] = v.x; py[k] = v.y;
    }
    const float4* t4 = reinterpret_cast<const float4*>(s_targ + lane * 8);
    float4 ta = t4[0];
    float4 tb = t4[1];

    // pred mean
    float sx = 0.f, sy = 0.f;
    #pragma unroll
    for (int k = 0; k < NUM_PTS; k++) { sx += px[k]; sy += py[k]; }
    const float inv_np = 1.0f / (float)NUM_PTS;
    float mux = sx * inv_np, muy = sy * inv_np;

    // pred covariance
    float cxx = 0.f, cxy = 0.f, cyy = 0.f;
    #pragma unroll
    for (int k = 0; k < NUM_PTS; k++) {
        float dx = px[k] - mux, dy = py[k] - muy;
        cxx += dx * dx; cxy += dx * dy; cyy += dy * dy;
    }
    cxx = cxx * inv_np + GMM_EPS_F;
    cxy = cxy * inv_np;
    cyy = cyy * inv_np + GMM_EPS_F;

    // target mean
    float tmux = (ta.x + ta.z + tb.x + tb.z) * 0.25f;
    float tmuy = (ta.y + ta.w + tb.y + tb.w) * 0.25f;

    // edges -> rotation * diag
    float e1x = ta.z - ta.x, e1y = ta.w - ta.y;
    float e2x = tb.x - ta.z, e2y = tb.y - ta.w;
    float w = e1x * e1x + e1y * e1y;
    float h = e2x * e2x + e2y * e2y;
    float inv_w = __frcp_rn(w);                 // 1/w (c2+s2 normalization)

    const float dscale = 1.0f / (4.0f * L_CONST * L_CONST);
    float d0 = w * dscale, d1 = h * dscale;

    // t_var = R diag(d) R^T with c=e1x/sqrt(w), s=e1y/sqrt(w):
    // c2 = e1x^2/w, s2 = e1y^2/w, cs = e1x*e1y/w
    float c2 = e1x * e1x * inv_w;
    float s2 = e1y * e1y * inv_w;
    float cs = e1x * e1y * inv_w;
    float t00 = c2 * d0 + s2 * d1;
    float t01 = cs * (d0 - d1);
    float t11 = s2 * d0 + c2 * d1;

    float t_det = t00 * t11 - t01 * t01;
    float p_det = cxx * cyy - cxy * cxy;

    // term1 + trace = [ t11*(dx^2+cxx) - 2*t01*(dx*dy+cxy) + t00*(dy^2+cyy) ] / t_det
    float dx = mux - tmux, dy = muy - tmuy;
    float q0 = fmaf(dx, dx, cxx);
    float q1 = fmaf(dx, dy, cxy);
    float q2 = fmaf(dy, dy, cyy);
    float num = t11 * q0 - 2.0f * t01 * q1 + t00 * q2;

    float sum12 = num * __frcp_rn(t_det) + (__logf(t_det) - __logf(p_det));

    float kld = 0.5f * sum12 - 1.0f;
    float kl_agg = fmaxf(kld, EPS_F);
    float sq = kl_agg * rsqrtf(kl_agg);          // sqrt(kl_agg), kl_agg >= 1e-6
    return __fdividef(1.0f + sq, 2.0f + sq);     // 1 - 1/(2+sq)
}

__global__ void __launch_bounds__(256) kld_loss_kernel(
    const float* __restrict__ pred,
    const float* __restrict__ target,
    float* __restrict__ out)
{
    // per-warp double-buffered slabs: 8 warps * 2 stages * 208 float4 = 53248 B
    extern __shared__ float4 s4[];

    const int tid  = threadIdx.x;
    const int lane = tid & 31;
    const int wid  = tid >> 5;
    float4* wslab = s4 + wid * (NSTAGE * WSTAGE_F4);

    const float4* gp_base = reinterpret_cast<const float4*>(pred);
    const float4* gt_base = reinterpret_cast<const float4*>(target);

    int c    = blockIdx.x * WARPS_PER_BLK + wid;
    int next = c + TOTAL_WARPS;
    int buf  = 0;

    issue_wchunk(wslab, gp_base + (size_t)c * WPRED_F4,
                        gt_base + (size_t)c * WTARG_F4, lane);

    float acc = 0.0f;

    while (c < NWCHUNK) {
        if (next < NWCHUNK) {
            issue_wchunk(wslab + (buf ^ 1) * WSTAGE_F4,
                         gp_base + (size_t)next * WPRED_F4,
                         gt_base + (size_t)next * WTARG_F4, lane);
            cp_wait<1>();
        } else {
            cp_wait<0>();
        }
        __syncwarp();

        const float* stage = reinterpret_cast<const float*>(wslab + buf * WSTAGE_F4);
        acc += box_loss(stage, stage + WPRED_F4 * 4, lane);

        __syncwarp();   // all lanes done reading before this stage is reused

        c = next;
        next += TOTAL_WARPS;
        buf ^= 1;
    }

    // ---- block reduction ----
    #pragma unroll
    for (int off = 16; off > 0; off >>= 1)
        acc += __shfl_down_sync(0xFFFFFFFFu, acc, off);

    __shared__ float warp_sums[WARPS_PER_BLK];
    if (lane == 0) warp_sums[wid] = acc;
    __syncthreads();

    if (wid == 0) {
        float v = (lane < WARPS_PER_BLK) ? warp_sums[lane] : 0.0f;
        #pragma unroll
        for (int off = 4; off > 0; off >>= 1)
            v += __shfl_down_sync(0xFFFFFFFFu, v, off);
        if (lane == 0)
            atomicAdd(out, v * (1.0f / (float)N_BOX));
    }
}

extern "C" void kernel_launch(void* const* d_in, const int* in_sizes, int n_in,
                              void* d_out, int out_size) {
    const float* pred   = (const float*)d_in[0];
    const float* target = (const float*)d_in[1];
    float* out = (float*)d_out;

    static int configured = 0;
    if (!configured) {
        cudaFuncSetAttribute(kld_loss_kernel,
                             cudaFuncAttributeMaxDynamicSharedMemorySize,
                             WARPS_PER_BLK * NSTAGE * WSTAGE_F4 * sizeof(float4));
        configured = 1;
    }

    zero_out_kernel<<<1, 1>>>(out);
    kld_loss_kernel<<<GRID_BLKS, 256,
                      WARPS_PER_BLK * NSTAGE * WSTAGE_F4 * sizeof(float4)>>>(
        pred, target, out);
}